// round 5
// baseline (speedup 1.0000x reference)
#include <cuda_runtime.h>

#define NROWS 8192
#define D4 128              // 512 floats = 128 float4 per row
#define NBLOCKS 1024        // warp-per-row: 1024 * 8 warps = 8192 rows
#define NTHREADS 256
#define WARPS_PER_BLK 8

// Single 64-bit accumulator:
//   bits [52:64) : block-arrival counter (max 1024 < 2^12)
//   bits [0:52)  : biased fixed-point sum of cosines (scale 2^32, bias 2^36/block)
// Integer adds are exactly associative -> deterministic for any atomic order,
// and the atomic's return value carries the data -> no __threadfence needed.
__device__ unsigned long long g_accum = 0ull;

__global__ __launch_bounds__(NTHREADS) void byol_kernel(
    const float4* __restrict__ x, const float4* __restrict__ xt,
    float* __restrict__ out)
{
    __shared__ float s_cos[WARPS_PER_BLK];

    int warp = threadIdx.x >> 5;
    int lane = threadIdx.x & 31;
    int row  = blockIdx.x * WARPS_PER_BLK + warp;

    const float4* xr = x  + (size_t)row * D4 + lane;
    const float4* tr = xt + (size_t)row * D4 + lane;

    // Front-batch ALL 8 independent 128-bit loads (MLP = 8) before any math.
    float4 a0 = xr[0],  a1 = xr[32],  a2 = xr[64],  a3 = xr[96];
    float4 b0 = tr[0],  b1 = tr[32],  b2 = tr[64],  b3 = tr[96];

    float dot = 0.f, nx = 0.f, nt = 0.f;
    dot += a0.x*b0.x + a0.y*b0.y + a0.z*b0.z + a0.w*b0.w;
    nx  += a0.x*a0.x + a0.y*a0.y + a0.z*a0.z + a0.w*a0.w;
    nt  += b0.x*b0.x + b0.y*b0.y + b0.z*b0.z + b0.w*b0.w;
    dot += a1.x*b1.x + a1.y*b1.y + a1.z*b1.z + a1.w*b1.w;
    nx  += a1.x*a1.x + a1.y*a1.y + a1.z*a1.z + a1.w*a1.w;
    nt  += b1.x*b1.x + b1.y*b1.y + b1.z*b1.z + b1.w*b1.w;
    dot += a2.x*b2.x + a2.y*b2.y + a2.z*b2.z + a2.w*b2.w;
    nx  += a2.x*a2.x + a2.y*a2.y + a2.z*a2.z + a2.w*a2.w;
    nt  += b2.x*b2.x + b2.y*b2.y + b2.z*b2.z + b2.w*b2.w;
    dot += a3.x*b3.x + a3.y*b3.y + a3.z*b3.z + a3.w*b3.w;
    nx  += a3.x*a3.x + a3.y*a3.y + a3.z*a3.z + a3.w*a3.w;
    nt  += b3.x*b3.x + b3.y*b3.y + b3.z*b3.z + b3.w*b3.w;

    // Warp tree reduction (fixed order -> deterministic).
    #pragma unroll
    for (int off = 16; off > 0; off >>= 1) {
        dot += __shfl_xor_sync(0xffffffffu, dot, off);
        nx  += __shfl_xor_sync(0xffffffffu, nx,  off);
        nt  += __shfl_xor_sync(0xffffffffu, nt,  off);
    }

    if (lane == 0) {
        const float EPS = 1e-8f;
        float denom = fmaxf(sqrtf(nx), EPS) * fmaxf(sqrtf(nt), EPS);
        s_cos[warp] = dot / denom;
    }
    __syncthreads();

    if (threadIdx.x == 0) {
        // Block partial in double (exact fixed-point conversion).
        double p = 0.0;
        #pragma unroll
        for (int i = 0; i < WARPS_PER_BLK; i++) p += (double)s_cos[i];

        long long fixed = llrint(p * 4294967296.0);       // * 2^32, |.| < 2^35
        unsigned long long add =
            (1ull << 52) + (unsigned long long)(fixed + (1ll << 36));

        unsigned long long total = atomicAdd(&g_accum, add) + add;

        if ((total >> 52) == (unsigned long long)NBLOCKS) {
            // Last atomic in L2 serialization order: 'total' is the exact sum.
            long long sfix = (long long)(total & ((1ull << 52) - 1))
                           - ((long long)NBLOCKS << 36);   // remove biases
            double cos_sum = (double)sfix * (1.0 / 4294967296.0);
            out[0] = (float)(2.0 - 2.0 * cos_sum / (double)NROWS);
            // All 1024 adds have serialized before ours -> safe to reset.
            atomicExch(&g_accum, 0ull);
        }
    }
}

extern "C" void kernel_launch(void* const* d_in, const int* in_sizes, int n_in,
                              void* d_out, int out_size)
{
    const float4* x  = (const float4*)d_in[0];
    const float4* xt = (const float4*)d_in[1];
    float* out = (float*)d_out;

    byol_kernel<<<NBLOCKS, NTHREADS>>>(x, xt, out);
}

// round 8
// speedup vs baseline: 1.0239x; 1.0239x over previous
#include <cuda_runtime.h>
#include <cstdint>

#define NROWS 8192
#define ROW_BYTES 2048          // 512 floats
#define NBLOCKS 256
#define NTHREADS 128            // 4 warps, warp-per-row within a chunk
#define ROWS_PER_BLOCK 32       // 256 * 32 = 8192
#define CHUNK_ROWS 4
#define NCHUNKS 8               // ROWS_PER_BLOCK / CHUNK_ROWS
#define CHUNK_HALF (CHUNK_ROWS * ROW_BYTES)   // 8192 B  (x part)
#define STAGE_BYTES (2 * CHUNK_HALF)          // 16384 B (x + xt)

// Packed accumulator: bits[52:64) block counter, bits[0:52) biased fixed-point
// cosine sum (scale 2^32, bias 2^38/block). Integer adds are associative ->
// deterministic for any atomic order; return value carries data -> no fence.
__device__ unsigned long long g_accum = 0ull;

__device__ __forceinline__ uint32_t smem_u32(const void* p) {
    uint32_t a;
    asm("{ .reg .u64 t; cvta.to.shared.u64 t, %1; cvt.u32.u64 %0, t; }"
        : "=r"(a) : "l"(p));
    return a;
}

__device__ __forceinline__ void mbar_init(uint32_t mbar, uint32_t cnt) {
    asm volatile("mbarrier.init.shared.b64 [%0], %1;" :: "r"(mbar), "r"(cnt) : "memory");
}
__device__ __forceinline__ void mbar_expect_tx(uint32_t mbar, uint32_t bytes) {
    asm volatile("mbarrier.arrive.expect_tx.shared.b64 _, [%0], %1;"
                 :: "r"(mbar), "r"(bytes) : "memory");
}
__device__ __forceinline__ void mbar_wait(uint32_t mbar, uint32_t parity) {
    uint32_t done;
    asm volatile(
        "{\n\t.reg .pred p;\n\t"
        "mbarrier.try_wait.parity.acquire.cta.shared::cta.b64 p, [%1], %2;\n\t"
        "selp.b32 %0, 1, 0, p;\n\t}"
        : "=r"(done) : "r"(mbar), "r"(parity) : "memory");
    if (!done) {
        asm volatile(
            "{\n\t.reg .pred P1;\n\t"
            "WL_%=:\n\t"
            "mbarrier.try_wait.parity.acquire.cta.shared::cta.b64 P1, [%0], %1, 0x989680;\n\t"
            "@P1 bra.uni WD_%=;\n\t"
            "bra.uni WL_%=;\n\t"
            "WD_%=:\n\t}"
            :: "r"(mbar), "r"(parity) : "memory");
    }
}
__device__ __forceinline__ void bulk_copy(uint32_t dst_smem, const void* src, uint32_t bytes, uint32_t mbar) {
    asm volatile(
        "cp.async.bulk.shared::cluster.global.mbarrier::complete_tx::bytes [%0], [%1], %2, [%3];"
        :: "r"(dst_smem), "l"(src), "r"(bytes), "r"(mbar) : "memory");
}

__global__ __launch_bounds__(NTHREADS) void byol_tma_kernel(
    const float* __restrict__ x, const float* __restrict__ xt,
    float* __restrict__ out)
{
    __shared__ __align__(1024) unsigned char s_data[2][STAGE_BYTES];
    __shared__ __align__(8) unsigned long long s_full[2];
    __shared__ float s_cos[NTHREADS / 32];

    int tid  = threadIdx.x;
    int warp = tid >> 5;
    int lane = tid & 31;

    uint32_t full0 = smem_u32(&s_full[0]);
    uint32_t full1 = smem_u32(&s_full[1]);
    uint32_t stage_addr[2] = { smem_u32(&s_data[0][0]), smem_u32(&s_data[1][0]) };

    const char* xb  = (const char*)x  + (size_t)blockIdx.x * ROWS_PER_BLOCK * ROW_BYTES;
    const char* tb  = (const char*)xt + (size_t)blockIdx.x * ROWS_PER_BLOCK * ROW_BYTES;

    if (tid == 0) {
        mbar_init(full0, 1);
        mbar_init(full1, 1);
        asm volatile("fence.proxy.async.shared::cta;" ::: "memory");
    }
    __syncthreads();

    // Prologue: prefetch chunks 0 and 1.
    if (tid == 0) {
        mbar_expect_tx(full0, STAGE_BYTES);
        bulk_copy(stage_addr[0],              xb + 0 * CHUNK_HALF, CHUNK_HALF, full0);
        bulk_copy(stage_addr[0] + CHUNK_HALF, tb + 0 * CHUNK_HALF, CHUNK_HALF, full0);
        mbar_expect_tx(full1, STAGE_BYTES);
        bulk_copy(stage_addr[1],              xb + 1 * CHUNK_HALF, CHUNK_HALF, full1);
        bulk_copy(stage_addr[1] + CHUNK_HALF, tb + 1 * CHUNK_HALF, CHUNK_HALF, full1);
    }

    float csum = 0.f;   // lane 0 of each warp accumulates its cosines

    for (int c = 0; c < NCHUNKS; c++) {
        int st = c & 1;
        uint32_t ph = (c >> 1) & 1;
        mbar_wait(st ? full1 : full0, ph);

        // Warp 'warp' reduces row 'warp' of this chunk.
        const float4* xr = (const float4*)(s_data[st] + warp * ROW_BYTES);
        const float4* tr = (const float4*)(s_data[st] + CHUNK_HALF + warp * ROW_BYTES);

        float4 a0 = xr[lane], a1 = xr[lane + 32], a2 = xr[lane + 64], a3 = xr[lane + 96];
        float4 b0 = tr[lane], b1 = tr[lane + 32], b2 = tr[lane + 64], b3 = tr[lane + 96];

        float dot = 0.f, nx = 0.f, nt = 0.f;
        dot += a0.x*b0.x + a0.y*b0.y + a0.z*b0.z + a0.w*b0.w;
        nx  += a0.x*a0.x + a0.y*a0.y + a0.z*a0.z + a0.w*a0.w;
        nt  += b0.x*b0.x + b0.y*b0.y + b0.z*b0.z + b0.w*b0.w;
        dot += a1.x*b1.x + a1.y*b1.y + a1.z*b1.z + a1.w*b1.w;
        nx  += a1.x*a1.x + a1.y*a1.y + a1.z*a1.z + a1.w*a1.w;
        nt  += b1.x*b1.x + b1.y*b1.y + b1.z*b1.z + b1.w*b1.w;
        dot += a2.x*b2.x + a2.y*b2.y + a2.z*b2.z + a2.w*b2.w;
        nx  += a2.x*a2.x + a2.y*a2.y + a2.z*a2.z + a2.w*a2.w;
        nt  += b2.x*b2.x + b2.y*b2.y + b2.z*b2.z + b2.w*b2.w;
        dot += a3.x*b3.x + a3.y*b3.y + a3.z*b3.z + a3.w*b3.w;
        nx  += a3.x*a3.x + a3.y*a3.y + a3.z*a3.z + a3.w*a3.w;
        nt  += b3.x*b3.x + b3.y*b3.y + b3.z*b3.z + b3.w*b3.w;

        #pragma unroll
        for (int off = 16; off > 0; off >>= 1) {
            dot += __shfl_xor_sync(0xffffffffu, dot, off);
            nx  += __shfl_xor_sync(0xffffffffu, nx,  off);
            nt  += __shfl_xor_sync(0xffffffffu, nt,  off);
        }

        if (lane == 0) {
            const float EPS = 1e-8f;
            float denom = fmaxf(sqrtf(nx), EPS) * fmaxf(sqrtf(nt), EPS);
            csum += dot / denom;
        }

        __syncthreads();   // all warps done reading stage 'st'

        if (tid == 0 && c + 2 < NCHUNKS) {
            uint32_t fb = st ? full1 : full0;
            mbar_expect_tx(fb, STAGE_BYTES);
            bulk_copy(stage_addr[st],              xb + (size_t)(c + 2) * CHUNK_HALF, CHUNK_HALF, fb);
            bulk_copy(stage_addr[st] + CHUNK_HALF, tb + (size_t)(c + 2) * CHUNK_HALF, CHUNK_HALF, fb);
        }
    }

    if (lane == 0) s_cos[warp] = csum;
    __syncthreads();

    if (tid == 0) {
        double p = 0.0;
        #pragma unroll
        for (int i = 0; i < NTHREADS / 32; i++) p += (double)s_cos[i];

        long long fixed = llrint(p * 4294967296.0);   // * 2^32, |.| < 2^37
        unsigned long long add =
            (1ull << 52) + (unsigned long long)(fixed + (1ll << 38));

        unsigned long long total = atomicAdd(&g_accum, add) + add;

        if ((total >> 52) == (unsigned long long)NBLOCKS) {
            long long sfix = (long long)(total & ((1ull << 52) - 1))
                           - ((long long)NBLOCKS << 38);
            double cos_sum = (double)sfix * (1.0 / 4294967296.0);
            out[0] = (float)(2.0 - 2.0 * cos_sum / (double)NROWS);
            atomicExch(&g_accum, 0ull);   // all adds already serialized; reset for replay
        }
    }
}

extern "C" void kernel_launch(void* const* d_in, const int* in_sizes, int n_in,
                              void* d_out, int out_size)
{
    const float* x  = (const float*)d_in[0];
    const float* xt = (const float*)d_in[1];
    float* out = (float*)d_out;

    byol_tma_kernel<<<NBLOCKS, NTHREADS>>>(x, xt, out);
}

// round 9
// speedup vs baseline: 1.2657x; 1.2362x over previous
#include <cuda_runtime.h>
#include <cstdint>

#define NROWS 8192
#define D4 128              // 512 floats = 128 float4 per row
#define NBLOCKS 1024        // warp-per-row: 1024 * 8 warps = 8192 rows
#define NTHREADS 256
#define WARPS_PER_BLK 8

// Packed accumulator: bits[52:64) block counter, bits[0:52) biased fixed-point
// cosine sum (scale 2^32, bias 2^36/block). Integer adds are exactly
// associative -> deterministic for any atomic order; the atomic's return value
// carries the data -> no __threadfence needed. Self-resets for graph replay.
__device__ unsigned long long g_accum = 0ull;

// Un-sinkable 128-bit load: volatile asm pins issue order, forcing ptxas to
// keep all batched loads in flight simultaneously (true MLP = batch size).
__device__ __forceinline__ float4 ldg128(const float4* p) {
    float4 v;
    asm volatile("ld.global.nc.v4.f32 {%0,%1,%2,%3}, [%4];"
                 : "=f"(v.x), "=f"(v.y), "=f"(v.z), "=f"(v.w)
                 : "l"(p));
    return v;
}

__global__ __launch_bounds__(NTHREADS) void byol_kernel(
    const float4* __restrict__ x, const float4* __restrict__ xt,
    float* __restrict__ out)
{
    __shared__ float s_cos[WARPS_PER_BLK];

    int warp = threadIdx.x >> 5;
    int lane = threadIdx.x & 31;
    int row  = blockIdx.x * WARPS_PER_BLK + warp;

    const float4* xr = x  + (size_t)row * D4 + lane;
    const float4* tr = xt + (size_t)row * D4 + lane;

    // All 8 independent LDG.128s issued back-to-back (un-sinkable).
    float4 a0 = ldg128(xr +  0);
    float4 a1 = ldg128(xr + 32);
    float4 a2 = ldg128(xr + 64);
    float4 a3 = ldg128(xr + 96);
    float4 b0 = ldg128(tr +  0);
    float4 b1 = ldg128(tr + 32);
    float4 b2 = ldg128(tr + 64);
    float4 b3 = ldg128(tr + 96);

    float dot = 0.f, nx = 0.f, nt = 0.f;
    dot += a0.x*b0.x + a0.y*b0.y + a0.z*b0.z + a0.w*b0.w;
    nx  += a0.x*a0.x + a0.y*a0.y + a0.z*a0.z + a0.w*a0.w;
    nt  += b0.x*b0.x + b0.y*b0.y + b0.z*b0.z + b0.w*b0.w;
    dot += a1.x*b1.x + a1.y*b1.y + a1.z*b1.z + a1.w*b1.w;
    nx  += a1.x*a1.x + a1.y*a1.y + a1.z*a1.z + a1.w*a1.w;
    nt  += b1.x*b1.x + b1.y*b1.y + b1.z*b1.z + b1.w*b1.w;
    dot += a2.x*b2.x + a2.y*b2.y + a2.z*b2.z + a2.w*b2.w;
    nx  += a2.x*a2.x + a2.y*a2.y + a2.z*a2.z + a2.w*a2.w;
    nt  += b2.x*b2.x + b2.y*b2.y + b2.z*b2.z + b2.w*b2.w;
    dot += a3.x*b3.x + a3.y*b3.y + a3.z*b3.z + a3.w*b3.w;
    nx  += a3.x*a3.x + a3.y*a3.y + a3.z*a3.z + a3.w*a3.w;
    nt  += b3.x*b3.x + b3.y*b3.y + b3.z*b3.z + b3.w*b3.w;

    // Warp tree reduction (fixed order -> deterministic).
    #pragma unroll
    for (int off = 16; off > 0; off >>= 1) {
        dot += __shfl_xor_sync(0xffffffffu, dot, off);
        nx  += __shfl_xor_sync(0xffffffffu, nx,  off);
        nt  += __shfl_xor_sync(0xffffffffu, nt,  off);
    }

    if (lane == 0) {
        const float EPS = 1e-8f;
        float denom = fmaxf(sqrtf(nx), EPS) * fmaxf(sqrtf(nt), EPS);
        s_cos[warp] = dot / denom;
    }
    __syncthreads();

    if (threadIdx.x == 0) {
        // Block partial in double (exact fixed-point conversion).
        double p = 0.0;
        #pragma unroll
        for (int i = 0; i < WARPS_PER_BLK; i++) p += (double)s_cos[i];

        long long fixed = llrint(p * 4294967296.0);       // * 2^32, |.| < 2^35
        unsigned long long add =
            (1ull << 52) + (unsigned long long)(fixed + (1ll << 36));

        unsigned long long total = atomicAdd(&g_accum, add) + add;

        if ((total >> 52) == (unsigned long long)NBLOCKS) {
            // Last atomic in L2 serialization order: 'total' is the exact sum.
            long long sfix = (long long)(total & ((1ull << 52) - 1))
                           - ((long long)NBLOCKS << 36);   // remove biases
            double cos_sum = (double)sfix * (1.0 / 4294967296.0);
            out[0] = (float)(2.0 - 2.0 * cos_sum / (double)NROWS);
            // All 1024 adds already serialized through L2 -> safe to reset.
            atomicExch(&g_accum, 0ull);
        }
    }
}

extern "C" void kernel_launch(void* const* d_in, const int* in_sizes, int n_in,
                              void* d_out, int out_size)
{
    const float4* x  = (const float4*)d_in[0];
    const float4* xt = (const float4*)d_in[1];
    float* out = (float*)d_out;

    byol_kernel<<<NBLOCKS, NTHREADS>>>(x, xt, out);
}